// round 16
// baseline (speedup 1.0000x reference)
#include <cuda_runtime.h>
#include <cuda_bf16.h>
#include <math.h>
#include <stdint.h>

#define BB 4
#define INCH 256
#define NPTS 2048
#define NP1 2049
#define DIM 256
#define KNN 16
#define PHID 64
#define HID 1024
#define NCOL (BB*NP1*KNN)   /* 131136 */
#define NK   (BB*NPTS*KNN)  /* 131072 */
#define NCH  8
#define EPSV 1e-5f
#define GSMEM  81920
#define GSMEMB 81920

// ---------------- scratch ----------------------------------------------------
__device__ float g_xT[BB*NPTS*INCH];
__device__ float g_hx[BB*NP1*DIM];
__device__ __nv_bfloat16 g_qb[BB*NP1*DIM];
__device__ __nv_bfloat16 g_kb[BB*NP1*DIM];
__device__ float g_v [BB*NP1*DIM];
__device__ int   g_idx[BB*NPTS*KNN];
__device__ float g_pd[BB*NPTS*NCH*KNN];
__device__ int   g_pi[BB*NPTS*NCH*KNN];
__device__ __nv_bfloat16 g_phb[NK*PHID];
__device__ __nv_bfloat16 g_pe [(long)NK*DIM];
__device__ __nv_bfloat16 g_hid[(long)NCOL*HID];
__device__ float g_agg[BB*NP1*DIM];
__device__ float g_y  [BB*NP1*DIM];
__device__ __nv_bfloat16 g_w1q[BB*NP1*HID];
__device__ __nv_bfloat16 g_w1k[BB*NPTS*HID];
__device__ __nv_bfloat16 g_bWc[HID*PHID];
__device__ __nv_bfloat16 g_bW2[DIM*HID];
__device__ __nv_bfloat16 g_bW1[HID*DIM];
__device__ __nv_bfloat16 g_bP2[DIM*PHID];
__device__ float g_sA[HID], g_tA[HID], g_w1pb[HID];
__device__ float g_sP[PHID], g_tP[PHID];
__device__ float g_rWs[DIM*INCH];
__device__ float g_rWq[DIM*DIM];
__device__ float g_rWk[DIM*DIM];
__device__ float g_rWv[DIM*DIM];
__device__ float g_rWe[INCH*DIM];

// ---------------- helpers ----------------------------------------------------
__device__ __forceinline__ float rtf(float x){
    uint32_t r; asm("cvt.rna.tf32.f32 %0, %1;" : "=r"(r) : "f"(x));
    return __uint_as_float(r);
}
__device__ __forceinline__ void mma_tf32(float&c0,float&c1,float&c2,float&c3,
   uint32_t a0,uint32_t a1,uint32_t a2,uint32_t a3,uint32_t b0,uint32_t b1){
  asm volatile("mma.sync.aligned.m16n8k8.row.col.f32.tf32.tf32.f32 "
    "{%0,%1,%2,%3}, {%4,%5,%6,%7}, {%8,%9}, {%0,%1,%2,%3};\n"
    : "+f"(c0),"+f"(c1),"+f"(c2),"+f"(c3)
    : "r"(a0),"r"(a1),"r"(a2),"r"(a3),"r"(b0),"r"(b1));
}
__device__ __forceinline__ void mma_bf16(float&c0,float&c1,float&c2,float&c3,
   uint32_t a0,uint32_t a1,uint32_t a2,uint32_t a3,uint32_t b0,uint32_t b1){
  asm volatile("mma.sync.aligned.m16n8k16.row.col.f32.bf16.bf16.f32 "
    "{%0,%1,%2,%3}, {%4,%5,%6,%7}, {%8,%9}, {%0,%1,%2,%3};\n"
    : "+f"(c0),"+f"(c1),"+f"(c2),"+f"(c3)
    : "r"(a0),"r"(a1),"r"(a2),"r"(a3),"r"(b0),"r"(b1));
}
__device__ __forceinline__ void ldsm4(uint32_t&r0,uint32_t&r1,uint32_t&r2,uint32_t&r3,
                                      uint32_t addr){
  asm volatile("ldmatrix.sync.aligned.m8n8.x4.shared.b16 {%0,%1,%2,%3}, [%4];"
    : "=r"(r0),"=r"(r1),"=r"(r2),"=r"(r3) : "r"(addr));
}
__device__ __forceinline__ void cp16(uint32_t dst, const void* src){
    asm volatile("cp.async.cg.shared.global [%0], [%1], 16;" :: "r"(dst), "l"(src));
}
__device__ __forceinline__ void cpcommit(){ asm volatile("cp.async.commit_group;"); }
__device__ __forceinline__ void cpwait2(){ asm volatile("cp.async.wait_group 2;"); }
__device__ __forceinline__ void cpwait0(){ asm volatile("cp.async.wait_group 0;"); }

// ---------------- merged weight rounding ------------------------------------
struct RCArgs {
    const float* s[5];
    float* d[5];
    int end[5];
};
__global__ void roundcpy_all_kernel(RCArgs a){
    int i = blockIdx.x*256 + threadIdx.x;
    int seg = 0;
#pragma unroll
    for (int k = 0; k < 5; k++) if (i >= a.end[k]) seg = k+1;
    if (seg >= 5) return;
    int base = seg ? a.end[seg-1] : 0;
    a.d[seg][i-base] = rtf(a.s[seg][i-base]);
}
__global__ void cvtb3_kernel(const float* __restrict__ a, __nv_bfloat16* __restrict__ da,
                             const float* __restrict__ b, __nv_bfloat16* __restrict__ db,
                             const float* __restrict__ c, __nv_bfloat16* __restrict__ dc,
                             int n1, int n2){
    int i = blockIdx.x*256 + threadIdx.x;
    if (i < n1)            da[i]      = __float2bfloat16_rn(a[i]);
    else if (i < n1+n2)    db[i-n1]   = __float2bfloat16_rn(b[i-n1]);
    else                   dc[i-n1-n2]= __float2bfloat16_rn(c[i-n1-n2]);
}

// ---------------- small prep kernels ----------------------------------------
__global__ void transpose_x_kernel(const float* __restrict__ x){
    __shared__ float tile[32][33];
    int b = blockIdx.z;
    int i0 = blockIdx.y*32, n0 = blockIdx.x*32;
    int tx = threadIdx.x, ty = threadIdx.y;
    tile[ty][tx] = x[(b*INCH + (i0+ty))*NPTS + n0+tx];
    __syncthreads();
    g_xT[(b*NPTS + (n0+ty))*INCH + i0+tx] = rtf(tile[tx][ty]);
}

__global__ void prep_kernel(const float* __restrict__ ag, const float* __restrict__ abeta,
                            const float* __restrict__ am, const float* __restrict__ av,
                            const float* __restrict__ ab1,
                            const float* __restrict__ pg, const float* __restrict__ pbeta,
                            const float* __restrict__ pm, const float* __restrict__ pv,
                            const float* __restrict__ pb1,
                            const float* __restrict__ W1, const float* __restrict__ pb2){
    int t = threadIdx.x;
    if (t < HID){
        float s = ag[t] / sqrtf(av[t] + EPSV);
        g_sA[t] = s;
        g_tA[t] = abeta[t] - am[t]*s + ab1[t]*s;
        float acc = 0.f;
        for (int c = 0; c < DIM; c++) acc += W1[t*DIM+c]*pb2[c];
        g_w1pb[t] = acc;
    }
    if (t < PHID){
        float s = pg[t] / sqrtf(pv[t] + EPSV);
        g_sP[t] = s;
        g_tP[t] = pbeta[t] - pm[t]*s + pb1[t]*s;
    }
}

__global__ void wc_kernel(const float* __restrict__ W1, const float* __restrict__ W2p){
    int h = blockIdx.x, p = threadIdx.x;
    float s = 0.f;
    for (int c = 0; c < DIM; c++) s += W1[h*DIM+c]*W2p[c*PHID+p];
    g_bWc[h*PHID+p] = __float2bfloat16_rn(s);
}

__global__ void init_cls_kernel(const float* __restrict__ cls){
    g_hx[(blockIdx.x*NP1)*DIM + threadIdx.x] = rtf(cls[threadIdx.x]);
}

__global__ void addpos_kernel(const float* __restrict__ pos_emb){
    int b = blockIdx.x, c = threadIdx.x;
    int o = (b*NP1)*DIM + c;
    g_qb[o] = __float2bfloat16_rn(__bfloat162float(g_qb[o]) + pos_emb[c]);
    g_v[o] += pos_emb[c];
}

// ---------------- KNN (chunked) ---------------------------------------------
__global__ __launch_bounds__(256) void knn_part_kernel(const float* __restrict__ pos){
    __shared__ float sx[256], sy[256], sz[256];
    int b = blockIdx.y, ch = blockIdx.z;
    const float* pb = pos + (size_t)b*3*NPTS;
    int j0 = ch*256;
    int t = threadIdx.x;
    sx[t] = pb[j0+t]; sy[t] = pb[NPTS+j0+t]; sz[t] = pb[2*NPTS+j0+t];
    __syncthreads();
    int qi = blockIdx.x*256 + t;
    float qx = pb[qi], qy = pb[NPTS+qi], qz = pb[2*NPTS+qi];
    float bd[KNN]; int bi[KNN];
#pragma unroll
    for (int i = 0; i < KNN; i++){ bd[i] = 3.4e38f; bi[i] = 0; }
    float maxv = 3.4e38f; int maxp = 0;
    for (int j = 0; j < 256; j++){
        float dx = qx - sx[j], dy = qy - sy[j], dz = qz - sz[j];
        float d = dx*dx + dy*dy + dz*dz;
        if (d < maxv){
            bd[maxp] = d; bi[maxp] = j0 + j;
            maxv = bd[0]; maxp = 0;
#pragma unroll
            for (int i = 1; i < KNN; i++)
                if (bd[i] > maxv){ maxv = bd[i]; maxp = i; }
        }
    }
    long base = ((long)(b*NPTS + qi)*NCH + ch)*KNN;
#pragma unroll
    for (int i = 0; i < KNN; i++){ g_pd[base+i] = bd[i]; g_pi[base+i] = bi[i]; }
}

__global__ __launch_bounds__(256) void knn_merge_kernel(){
    int b = blockIdx.y;
    int qi = blockIdx.x*256 + threadIdx.x;
    long base = (long)(b*NPTS + qi)*NCH*KNN;
    float bd[KNN]; int bi[KNN];
#pragma unroll
    for (int i = 0; i < KNN; i++){ bd[i] = 3.4e38f; bi[i] = 0; }
    float maxv = 3.4e38f; int maxp = 0;
    for (int j = 0; j < NCH*KNN; j++){
        float d = g_pd[base+j];
        if (d < maxv){
            bd[maxp] = d; bi[maxp] = g_pi[base+j];
            maxv = bd[0]; maxp = 0;
#pragma unroll
            for (int i = 1; i < KNN; i++)
                if (bd[i] > maxv){ maxv = bd[i]; maxp = i; }
        }
    }
    int ob = (b*NPTS + qi)*KNN;
#pragma unroll
    for (int i = 0; i < KNN; i++) g_idx[ob+i] = bi[i];
}

// ---------------- pos-MLP hidden (bf16 out) ----------------------------------
__global__ __launch_bounds__(256) void pos_hidden_kernel(const float* __restrict__ pos,
                                                         const float* __restrict__ pw1){
    int b = blockIdx.y, n = blockIdx.x;
    __shared__ float prx[KNN], pry[KNN], prz[KNN];
    int t = threadIdx.x;
    const float* pb = pos + (size_t)b*3*NPTS;
    if (t < KNN){
        int m = g_idx[(b*NPTS+n)*KNN + t];
        prx[t] = pb[n]        - pb[m];
        pry[t] = pb[NPTS+n]   - pb[NPTS+m];
        prz[t] = pb[2*NPTS+n] - pb[2*NPTS+m];
    }
    __syncthreads();
    for (int e = t; e < KNN*PHID; e += 256){
        int k = e >> 6, hh = e & 63;
        float z = pw1[hh*3+0]*prx[k] + pw1[hh*3+1]*pry[k] + pw1[hh*3+2]*prz[k];
        z = z*g_sP[hh] + g_tP[hh];
        z = fmaxf(z, 0.f);
        g_phb[((long)(b*NPTS+n)*KNN + k)*PHID + hh] = __float2bfloat16_rn(z);
    }
}

// ---------------- tf32 GEMM ---------------------------------------------------
// EPI 0: C = acc + bias[n] ; EPI 1: C = rtf(acc + bias[n]) ; EPI 5: bf16 out
template<int EPI>
__global__ __launch_bounds__(256,2) void gemm2(const float* __restrict__ A,
        const float* __restrict__ Bw, float* __restrict__ C,
        int M, int N, int K, const float* __restrict__ bias,
        long strideAb, long strideCb){
    extern __shared__ __align__(16) float sm[];
    A += (long)blockIdx.z*strideAb;
    C += (long)blockIdx.z*strideCb;
    const int t = threadIdx.x, lane = t&31, w = t>>5;
    const int wm = w>>2, wn = w&3;
    const int m0 = blockIdx.x*128, n0 = blockIdx.y*128;
    const uint32_t smb = (uint32_t)__cvta_generic_to_shared(sm);
    float acc[4][4][4];
#pragma unroll
    for (int i=0;i<4;i++)
#pragma unroll
      for (int j=0;j<4;j++)
#pragma unroll
        for (int c=0;c<4;c++) acc[i][j][c] = 0.f;

    const int nIter = K >> 4;
    auto prefetch = [&](int st, int kt){
#pragma unroll
        for (int l=0;l<2;l++){
            int g = t + (l<<8);
            int row = g>>2, kq = (g&3)<<2;
            int arow = m0 + row; if (arow >= M) arow = M - 1;
            uint32_t d = smb + (uint32_t)((st*5120 + row*20 + kq)<<2);
            cp16(d, A + (long)arow*K + (kt<<4) + kq);
            uint32_t d2 = smb + (uint32_t)((st*5120 + 2560 + row*20 + kq)<<2);
            cp16(d2, Bw + (long)(n0+row)*K + (kt<<4) + kq);
        }
        cpcommit();
    };
    prefetch(0, 0);
    prefetch(1, 1);
    prefetch(2, 2);

    for (int it = 0; it < nIter; ++it){
        if (it + 3 < nIter) cpwait2();
        else                cpwait0();
        __syncthreads();
        if (it+3 < nIter) prefetch((it+3)&3, it+3); else cpcommit();
        const float* sA = sm + (it&3)*5120;
        const float* sB = sA + 2560;
#pragma unroll
        for (int k8=0;k8<2;k8++){
            int kb = k8*8 + (lane&3);
            uint32_t af[4][4]; uint32_t bf[4][2];
#pragma unroll
            for (int i=0;i<4;i++){
                const float* p = sA + (wm*64 + i*16 + (lane>>2))*20 + kb;
                af[i][0]=__float_as_uint(p[0]);
                af[i][1]=__float_as_uint(p[160]);
                af[i][2]=__float_as_uint(p[4]);
                af[i][3]=__float_as_uint(p[164]);
            }
#pragma unroll
            for (int j=0;j<4;j++){
                const float* p = sB + (wn*32 + j*8 + (lane>>2))*20 + kb;
                bf[j][0]=__float_as_uint(p[0]);
                bf[j][1]=__float_as_uint(p[4]);
            }
#pragma unroll
            for (int i=0;i<4;i++)
#pragma unroll
                for (int j=0;j<4;j++)
                    mma_tf32(acc[i][j][0],acc[i][j][1],acc[i][j][2],acc[i][j][3],
                             af[i][0],af[i][1],af[i][2],af[i][3], bf[j][0],bf[j][1]);
        }
    }

    const int r0 = lane >> 2, cq = (lane & 3) << 1;
#pragma unroll
    for (int i=0;i<4;i++){
#pragma unroll
        for (int half=0; half<2; half++){
            int m = m0 + wm*64 + i*16 + r0 + half*8;
            if (m >= M) continue;
            if (EPI == 5){
                __nv_bfloat16* cb = (__nv_bfloat16*)C + (long)m*N;
#pragma unroll
                for (int j=0;j<4;j++){
                    int n = n0 + wn*32 + j*8 + cq;
                    float2 bv = *(const float2*)&bias[n];
                    __nv_bfloat162 o2 = __floats2bfloat162_rn(
                        acc[i][j][half*2+0] + bv.x, acc[i][j][half*2+1] + bv.y);
                    *(__nv_bfloat162*)&cb[n] = o2;
                }
            } else {
                float* crow = C + (long)m*N;
#pragma unroll
                for (int j=0;j<4;j++){
                    int n = n0 + wn*32 + j*8 + cq;
                    float2 o;
                    if (EPI == 0){
                        float2 bv = *(const float2*)&bias[n];
                        o.x = acc[i][j][half*2+0] + bv.x;
                        o.y = acc[i][j][half*2+1] + bv.y;
                    } else if (EPI == 1){
                        float2 bv = *(const float2*)&bias[n];
                        o.x = rtf(acc[i][j][half*2+0] + bv.x);
                        o.y = rtf(acc[i][j][half*2+1] + bv.y);
                    } else {
                        o.x = acc[i][j][half*2+0];
                        o.y = acc[i][j][half*2+1];
                    }
                    *(float2*)&crow[n] = o;
                }
            }
        }
    }
}

// ---------------- bf16 GEMM: m16n8k16 x2 per stage (k32), ldmatrix, 4-stage --
// EPI 2: folded attn-hidden -> g_hid (bf16)
// EPI 4: softmax+agg -> g_agg
// EPI 6: bf16 C = acc
// EPI 7: bf16 C = acc + bias[n]
template<int EPI>
__global__ __launch_bounds__(256,2) void gemm2b(const __nv_bfloat16* __restrict__ A,
        const __nv_bfloat16* __restrict__ Bw, float* __restrict__ C,
        int M, int N, int K, const float* __restrict__ bias,
        long strideAb, long strideCb){
    extern __shared__ __align__(16) uint32_t smw[];
    A += (long)blockIdx.z*strideAb;
    C += (long)blockIdx.z*strideCb;
    const int t = threadIdx.x, lane = t&31, w = t>>5;
    const int wm = w>>2, wn = w&3;
    const int m0 = blockIdx.x*128, n0 = blockIdx.y*128;
    const uint32_t smb = (uint32_t)__cvta_generic_to_shared(smw);
    float acc[4][4][4];
#pragma unroll
    for (int i=0;i<4;i++)
#pragma unroll
      for (int j=0;j<4;j++)
#pragma unroll
        for (int c=0;c<4;c++) acc[i][j][c] = 0.f;

    uint32_t aoff[4];
#pragma unroll
    for (int i=0;i<4;i++){
        int row = wm*64 + i*16 + (((lane>>3)&1)<<3) + (lane&7);
        aoff[i] = (uint32_t)(row*20 + ((lane>>4)<<2));
    }
    uint32_t boff[2];
#pragma unroll
    for (int jj=0;jj<2;jj++){
        int row = wn*32 + jj*16 + ((lane>>4)<<3) + (lane&7);
        boff[jj] = (uint32_t)(2560 + row*20 + (((lane>>3)&1)<<2));
    }

    const int nIter = K >> 5;
    auto prefetch = [&](int st, int kt){
        if (kt < nIter){
#pragma unroll
            for (int l=0;l<4;l++){
                int g = t + (l<<8);
                int row = g>>2;
                int kw  = (g&3)<<2;
                int kh  = (kt<<5) + ((g&3)<<3);
                if (row < 128){
                    int arow = m0 + row; if (arow >= M) arow = M - 1;
                    uint32_t d = smb + (uint32_t)((st*5120 + row*20 + kw)<<2);
                    cp16(d, A + (long)arow*K + kh);
                } else {
                    int brow = row - 128;
                    uint32_t d = smb + (uint32_t)((st*5120 + 2560 + brow*20 + kw)<<2);
                    cp16(d, Bw + (long)(n0+brow)*K + kh);
                }
            }
        }
        cpcommit();
    };
    prefetch(0, 0);
    prefetch(1, 1);
    prefetch(2, 2);

    for (int it = 0; it < nIter; ++it){
        if (it + 3 < nIter) cpwait2();
        else                cpwait0();
        __syncthreads();
        prefetch((it+3)&3, it+3);
        uint32_t sb = smb + (uint32_t)(((it&3)*5120)<<2);
#pragma unroll
        for (int s=0;s<2;s++){
            uint32_t so = sb + (uint32_t)(s*32);
            uint32_t af[4][4]; uint32_t bfr[2][4];
#pragma unroll
            for (int i=0;i<4;i++)
                ldsm4(af[i][0],af[i][1],af[i][2],af[i][3], so + (aoff[i]<<2));
#pragma unroll
            for (int jj=0;jj<2;jj++)
                ldsm4(bfr[jj][0],bfr[jj][1],bfr[jj][2],bfr[jj][3], so + (boff[jj]<<2));
#pragma unroll
            for (int i=0;i<4;i++)
#pragma unroll
                for (int j=0;j<4;j++)
                    mma_bf16(acc[i][j][0],acc[i][j][1],acc[i][j][2],acc[i][j][3],
                             af[i][0],af[i][1],af[i][2],af[i][3],
                             bfr[j>>1][(j&1)*2], bfr[j>>1][(j&1)*2+1]);
        }
    }

    const int r0 = lane >> 2, cq = (lane & 3) << 1;
    if (EPI == 4){
#pragma unroll
        for (int i=0;i<4;i++){
            int mrow = m0 + wm*64 + i*16;
            if (mrow >= M) continue;
            int colidx = mrow >> 4;
            int b  = colidx / NP1;
            int nn = colidx - b*NP1;
            long pebase = (nn > 0) ? (long)((b*NPTS + nn-1)*KNN)*DIM : 0;
            int kk0 = r0;
#pragma unroll
            for (int j=0;j<4;j++){
                int c0 = n0 + wn*32 + j*8 + cq;
                float outv[2];
#pragma unroll
                for (int q=0;q<2;q++){
                    float l0 = acc[i][j][q], l1 = acc[i][j][2+q];
                    float mx = fmaxf(l0, l1);
                    mx = fmaxf(mx, __shfl_xor_sync(0xffffffffu, mx, 4));
                    mx = fmaxf(mx, __shfl_xor_sync(0xffffffffu, mx, 8));
                    mx = fmaxf(mx, __shfl_xor_sync(0xffffffffu, mx, 16));
                    float e0 = expf(l0 - mx), e1 = expf(l1 - mx);
                    float pv0 = 0.f, pv1 = 0.f;
                    if (nn > 0){
                        pv0 = __bfloat162float(g_pe[pebase + (long)kk0*DIM + c0 + q]);
                        pv1 = __bfloat162float(g_pe[pebase + (long)(kk0+8)*DIM + c0 + q]);
                    }
                    float s  = e0 + e1;
                    float ts = e0*pv0 + e1*pv1;
                    s  += __shfl_xor_sync(0xffffffffu, s, 4);
                    ts += __shfl_xor_sync(0xffffffffu, ts, 4);
                    s  += __shfl_xor_sync(0xffffffffu, s, 8);
                    ts += __shfl_xor_sync(0xffffffffu, ts, 8);
                    s  += __shfl_xor_sync(0xffffffffu, s, 16);
                    ts += __shfl_xor_sync(0xffffffffu, ts, 16);
                    float vv = g_v[(long)colidx*DIM + c0 + q];
                    outv[q] = rtf(vv + ts / s);
                }
                if (r0 == 0){
                    float2 o = make_float2(outv[0], outv[1]);
                    *(float2*)&g_agg[(long)colidx*DIM + c0] = o;
                }
            }
        }
        return;
    }
#pragma unroll
    for (int i=0;i<4;i++){
#pragma unroll
        for (int half=0; half<2; half++){
            int m = m0 + wm*64 + i*16 + r0 + half*8;
            if (m >= M) continue;
            if (EPI == 2){
                int b  = m >> 15;
                int n  = (m >> 4) & (NPTS-1);
                int kk = m & 15;
                int midx = g_idx[((b*NPTS)+n)*KNN + kk];
                const __nv_bfloat16* wq = g_w1q + (long)(b*NP1 + n + 1)*HID;
                const __nv_bfloat16* wk = g_w1k + (long)(b*NPTS + midx)*HID;
                __nv_bfloat16* dst = g_hid + (long)((b*NP1 + n + 1)*KNN + kk)*HID;
#pragma unroll
                for (int j=0;j<4;j++){
                    int h = n0 + wn*32 + j*8 + cq;
                    float2 q2 = __bfloat1622float2(*(const __nv_bfloat162*)&wq[h]);
                    float2 k2 = __bfloat1622float2(*(const __nv_bfloat162*)&wk[h]);
                    float2 p2 = *(const float2*)&g_w1pb[h];
                    float2 s2 = *(const float2*)&g_sA[h];
                    float2 t2 = *(const float2*)&g_tA[h];
                    float ox = fmaxf((acc[i][j][half*2+0] + q2.x - k2.x + p2.x)*s2.x + t2.x, 0.f);
                    float oy = fmaxf((acc[i][j][half*2+1] + q2.y - k2.y + p2.y)*s2.y + t2.y, 0.f);
                    __nv_bfloat162 o2 = __floats2bfloat162_rn(ox, oy);
                    *(__nv_bfloat162*)&dst[h] = o2;
                }
            } else if (EPI == 6){
                __nv_bfloat16* cb = (__nv_bfloat16*)C + (long)m*N;
#pragma unroll
                for (int j=0;j<4;j++){
                    int n = n0 + wn*32 + j*8 + cq;
                    __nv_bfloat162 o2 = __floats2bfloat162_rn(
                        acc[i][j][half*2+0], acc[i][j][half*2+1]);
                    *(__nv_bfloat162*)&cb[n] = o2;
                }
            } else {                      // EPI 7: bf16 C = acc + bias
                __nv_bfloat16* cb = (__nv_bfloat16*)C + (long)m*N;
#pragma unroll
                for (int j=0;j<4;j++){
                    int n = n0 + wn*32 + j*8 + cq;
                    float2 bv = *(const float2*)&bias[n];
                    __nv_bfloat162 o2 = __floats2bfloat162_rn(
                        acc[i][j][half*2+0] + bv.x, acc[i][j][half*2+1] + bv.y);
                    *(__nv_bfloat162*)&cb[n] = o2;
                }
            }
        }
    }
}

// ---------------- cls hidden -------------------------------------------------
__global__ void cls_hidden_kernel(){
    int b = blockIdx.x >> 4, kk = blockIdx.x & 15;
    long col = (long)(b*NP1)*KNN + kk;
    for (int h = threadIdx.x; h < HID; h += 256){
        float wq = __bfloat162float(g_w1q[(long)(b*NP1)*HID + h]);
        float v = fmaxf(wq*g_sA[h] + g_tA[h], 0.f);
        g_hid[col*HID + h] = __float2bfloat16_rn(v);
    }
}

// ---------------- finalize outputs ------------------------------------------
__global__ void finalize1_kernel(const float* __restrict__ x, float* __restrict__ out){
    int gid = blockIdx.x*256 + threadIdx.x;
    int n  = gid % NPTS;
    int ch = (gid / NPTS) % DIM;
    int b  = gid / (NPTS*DIM);
    out[gid] = g_y[((b*NP1) + (n+1))*DIM + ch] + x[gid];
}
__global__ void finalize2_kernel(float* __restrict__ out){
    int t = threadIdx.x;
    int b = t / DIM, ch = t % DIM;
    out[BB*DIM*NPTS + t] = g_y[(b*NP1)*DIM + ch];
}

// ---------------- launch -----------------------------------------------------
extern "C" void kernel_launch(void* const* d_in, const int* in_sizes, int n_in,
                              void* d_out, int out_size){
    const float* x        = (const float*)d_in[0];
    const float* pos      = (const float*)d_in[1];
    const float* W_start  = (const float*)d_in[2];
    const float* b_start  = (const float*)d_in[3];
    const float* W_key    = (const float*)d_in[4];
    const float* b_key    = (const float*)d_in[5];
    const float* W_query  = (const float*)d_in[6];
    const float* b_query  = (const float*)d_in[7];
    const float* W_value  = (const float*)d_in[8];
    const float* b_value  = (const float*)d_in[9];
    const float* pos_W1   = (const float*)d_in[10];
    const float* pos_b1   = (const float*)d_in[11];
    const float* pos_g    = (const float*)d_in[12];
    const float* pos_beta = (const float*)d_in[13];
    const float* pos_m    = (const float*)d_in[14];
    const float* pos_v    = (const float*)d_in[15];
    const float* pos_W2   = (const float*)d_in[16];
    const float* pos_b2   = (const float*)d_in[17];
    const float* attn_W1  = (const float*)d_in[18];
    const float* attn_b1  = (const float*)d_in[19];
    const float* attn_g   = (const float*)d_in[20];
    const float* attn_beta= (const float*)d_in[21];
    const float* attn_m   = (const float*)d_in[22];
    const float* attn_v   = (const float*)d_in[23];
    const float* attn_W2  = (const float*)d_in[24];
    const float* attn_b2  = (const float*)d_in[25];
    const float* W_end    = (const float*)d_in[26];
    const float* b_end    = (const float*)d_in[27];
    const float* pos_emb  = (const float*)d_in[28];
    const float* cls_tok  = (const float*)d_in[29];
    float* out = (float*)d_out;
    (void)attn_b2;

    float *pxT,*phx,*pv,*pagg,*py;
    float *prWs,*prWq,*prWk,*prWv,*prWe;
    __nv_bfloat16 *pphb,*ppe,*phid,*pbWc,*pbW2,*pbW1,*pbP2,*pqb,*pkb,*pw1q,*pw1k;
    cudaGetSymbolAddress((void**)&pxT,  g_xT);
    cudaGetSymbolAddress((void**)&phx,  g_hx);
    cudaGetSymbolAddress((void**)&pqb,  g_qb);
    cudaGetSymbolAddress((void**)&pkb,  g_kb);
    cudaGetSymbolAddress((void**)&pv,   g_v);
    cudaGetSymbolAddress((void**)&pphb, g_phb);
    cudaGetSymbolAddress((void**)&ppe,  g_pe);
    cudaGetSymbolAddress((void**)&phid, g_hid);
    cudaGetSymbolAddress((void**)&pagg, g_agg);
    cudaGetSymbolAddress((void**)&py,   g_y);
    cudaGetSymbolAddress((void**)&pw1q, g_w1q);
    cudaGetSymbolAddress((void**)&pw1k, g_w1k);
    cudaGetSymbolAddress((void**)&pbWc, g_bWc);
    cudaGetSymbolAddress((void**)&pbW2, g_bW2);
    cudaGetSymbolAddress((void**)&pbW1, g_bW1);
    cudaGetSymbolAddress((void**)&pbP2, g_bP2);
    cudaGetSymbolAddress((void**)&prWs, g_rWs);
    cudaGetSymbolAddress((void**)&prWq, g_rWq);
    cudaGetSymbolAddress((void**)&prWk, g_rWk);
    cudaGetSymbolAddress((void**)&prWv, g_rWv);
    cudaGetSymbolAddress((void**)&prWe, g_rWe);

    cudaFuncSetAttribute(gemm2<0>, cudaFuncAttributeMaxDynamicSharedMemorySize, GSMEM);
    cudaFuncSetAttribute(gemm2<1>, cudaFuncAttributeMaxDynamicSharedMemorySize, GSMEM);
    cudaFuncSetAttribute(gemm2<5>, cudaFuncAttributeMaxDynamicSharedMemorySize, GSMEM);
    cudaFuncSetAttribute(gemm2b<2>, cudaFuncAttributeMaxDynamicSharedMemorySize, GSMEMB);
    cudaFuncSetAttribute(gemm2b<4>, cudaFuncAttributeMaxDynamicSharedMemorySize, GSMEMB);
    cudaFuncSetAttribute(gemm2b<6>, cudaFuncAttributeMaxDynamicSharedMemorySize, GSMEMB);
    cudaFuncSetAttribute(gemm2b<7>, cudaFuncAttributeMaxDynamicSharedMemorySize, GSMEMB);

    // ---- single-stream launch order (capture-safe) -------------------------
    transpose_x_kernel<<<dim3(NPTS/32, INCH/32, BB), dim3(32,32)>>>(x);
    prep_kernel<<<1,1024>>>(attn_g, attn_beta, attn_m, attn_v, attn_b1,
                            pos_g, pos_beta, pos_m, pos_v, pos_b1,
                            attn_W1, pos_b2);
    wc_kernel<<<HID, PHID>>>(attn_W1, pos_W2);
    cvtb3_kernel<<<(2*DIM*HID + DIM*PHID + 255)/256, 256>>>(
        attn_W2, pbW2, attn_W1, pbW1, pos_W2, pbP2, DIM*HID, HID*DIM);
    {
        RCArgs rc;
        rc.s[0]=W_start; rc.d[0]=prWs;
        rc.s[1]=W_query; rc.d[1]=prWq;
        rc.s[2]=W_key;   rc.d[2]=prWk;
        rc.s[3]=W_value; rc.d[3]=prWv;
        rc.s[4]=W_end;   rc.d[4]=prWe;
        int sz[5] = {DIM*INCH, DIM*DIM, DIM*DIM, DIM*DIM, INCH*DIM};
        int acc = 0;
        for (int k = 0; k < 5; k++){ acc += sz[k]; rc.end[k] = acc; }
        roundcpy_all_kernel<<<(acc + 255)/256, 256>>>(rc);
    }
    init_cls_kernel<<<BB, DIM>>>(cls_tok);
    knn_part_kernel<<<dim3(NPTS/256, BB, NCH), 256>>>(pos);
    knn_merge_kernel<<<dim3(NPTS/256, BB), 256>>>();

    // hx[1:] = W_start @ x + b
    gemm2<1><<<dim3(NPTS/128, DIM/128, BB), 256, GSMEM>>>(
        pxT, prWs, phx + DIM, NPTS, DIM, INCH, b_start,
        (long)NPTS*INCH, (long)NP1*DIM);

    // q,k (bf16 out) ; v (fp32, critical)
    gemm2<5><<<dim3((BB*NP1+127)/128, DIM/128, 1), 256, GSMEM>>>(
        phx, prWq, (float*)pqb, BB*NP1, DIM, DIM, b_query, 0, 0);
    gemm2<5><<<dim3((BB*NP1+127)/128, DIM/128, 1), 256, GSMEM>>>(
        phx, prWk, (float*)pkb, BB*NP1, DIM, DIM, b_key, 0, 0);
    gemm2<0><<<dim3((BB*NP1+127)/128, DIM/128, 1), 256, GSMEM>>>(
        phx, prWv, pv, BB*NP1, DIM, DIM, b_value, 0, 0);

    addpos_kernel<<<BB, DIM>>>(pos_emb);

    // w1q, w1k (bf16 cores, bf16 out)
    gemm2b<6><<<dim3((BB*NP1+127)/128, HID/128, 1), 256, GSMEMB>>>(
        pqb, pbW1, (float*)pw1q, BB*NP1, HID, DIM, nullptr, 0, 0);
    gemm2b<6><<<dim3(NPTS/128, HID/128, BB), 256, GSMEMB>>>(
        pkb + DIM, pbW1, (float*)pw1k, NPTS, HID, DIM, nullptr,
        (long)NP1*DIM, (long)NPTS*HID/2);

    // pos-MLP (bf16 core, bf16 out + bias)
    pos_hidden_kernel<<<dim3(NPTS, BB), 256>>>(pos, pos_W1);
    gemm2b<7><<<dim3(NK/128, DIM/128, 1), 256, GSMEMB>>>(
        pphb, pbP2, (float*)ppe, NK, DIM, PHID, pos_b2, 0, 0);

    // folded attn hidden (bf16 core)
    gemm2b<2><<<dim3(NK/128, HID/128, 1), 256, GSMEMB>>>(
        pphb, pbWc, nullptr, NK, HID, PHID, nullptr, 0, 0);
    cls_hidden_kernel<<<BB*KNN, 256>>>();

    // logits + fused softmax/aggregate (bf16 core)
    gemm2b<4><<<dim3((NCOL+127)/128, DIM/128, 1), 256, GSMEMB>>>(
        phid, pbW2, nullptr, NCOL, DIM, HID, nullptr, 0, 0);

    // y = W_end @ agg + b (tf32, critical)
    gemm2<0><<<dim3((BB*NP1+127)/128, DIM/128, 1), 256, GSMEM>>>(
        pagg, prWe, py, BB*NP1, DIM, DIM, b_end, 0, 0);

    finalize1_kernel<<<(BB*DIM*NPTS)/256, 256>>>(x, out);
    finalize2_kernel<<<1, BB*DIM>>>(out);
}